// round 1
// baseline (speedup 1.0000x reference)
#include <cuda_runtime.h>

// Problem constants (fixed by the reference: S=64, B=128, D=10000)
#define D_DIM   10000
#define D4      2500          // D/4 float4 elements per row
#define S_DIM   64
#define B_DIM   128
#define NROWS   (S_DIM * B_DIM)   // 8192
#define THREADS 256
#define NWARPS  (THREADS / 32)

// Scratch for per-row partial losses (no cudaMalloc allowed)
__device__ float g_partial[NROWS];

__global__ __launch_bounds__(THREADS)
void perturbed_loss_row_kernel(const float* __restrict__ theta,
                               const float* __restrict__ y,
                               const float* __restrict__ noise)
{
    extern __shared__ float sm[];           // 10000 floats = 40000 bytes
    __shared__ float red_max[NWARPS];
    __shared__ float red_sum[NWARPS];
    __shared__ float red_acc[NWARPS];

    const int row  = blockIdx.x;            // row = s*B + b
    const int b    = row & (B_DIM - 1);
    const int tid  = threadIdx.x;
    const int lane = tid & 31;
    const int warp = tid >> 5;

    const float4* __restrict__ th4 = (const float4*)(theta + (size_t)b   * D_DIM);
    const float4* __restrict__ yy4 = (const float4*)(y     + (size_t)b   * D_DIM);
    const float4* __restrict__ nz4 = (const float4*)(noise + (size_t)row * D_DIM);
    float4* sm4 = (float4*)sm;

    // ---- Pass 1: eta = theta + noise -> shared; running max ----
    float mx = -3.0e38f;
    for (int i = tid; i < D4; i += THREADS) {
        float4 t = th4[i];
        float4 n = nz4[i];
        float4 e;
        e.x = t.x + n.x;
        e.y = t.y + n.y;
        e.z = t.z + n.z;
        e.w = t.w + n.w;
        sm4[i] = e;
        mx = fmaxf(mx, fmaxf(fmaxf(e.x, e.y), fmaxf(e.z, e.w)));
    }
    #pragma unroll
    for (int o = 16; o; o >>= 1) mx = fmaxf(mx, __shfl_xor_sync(0xffffffffu, mx, o));
    if (lane == 0) red_max[warp] = mx;
    __syncthreads();
    mx = red_max[0];
    #pragma unroll
    for (int w = 1; w < NWARPS; w++) mx = fmaxf(mx, red_max[w]);

    // ---- Pass 2: exp(eta - mx) in place; row sum ----
    float sum = 0.0f;
    for (int i = tid; i < D4; i += THREADS) {
        float4 e = sm4[i];
        e.x = __expf(e.x - mx);
        e.y = __expf(e.y - mx);
        e.z = __expf(e.z - mx);
        e.w = __expf(e.w - mx);
        sm4[i] = e;
        sum += (e.x + e.y) + (e.z + e.w);
    }
    #pragma unroll
    for (int o = 16; o; o >>= 1) sum += __shfl_xor_sync(0xffffffffu, sum, o);
    if (lane == 0) red_sum[warp] = sum;
    __syncthreads();
    sum = red_sum[0];
    #pragma unroll
    for (int w = 1; w < NWARPS; w++) sum += red_sum[w];

    const float inv = __frcp_rn(sum);

    // ---- Pass 3: sum((pi - y)^2) ----
    float acc = 0.0f;
    for (int i = tid; i < D4; i += THREADS) {
        float4 e  = sm4[i];
        float4 yv = yy4[i];
        float dx = fmaf(e.x, inv, -yv.x);
        float dy = fmaf(e.y, inv, -yv.y);
        float dz = fmaf(e.z, inv, -yv.z);
        float dw = fmaf(e.w, inv, -yv.w);
        acc = fmaf(dx, dx, acc);
        acc = fmaf(dy, dy, acc);
        acc = fmaf(dz, dz, acc);
        acc = fmaf(dw, dw, acc);
    }
    #pragma unroll
    for (int o = 16; o; o >>= 1) acc += __shfl_xor_sync(0xffffffffu, acc, o);
    if (lane == 0) red_acc[warp] = acc;
    __syncthreads();
    if (tid == 0) {
        float total = red_acc[0];
        #pragma unroll
        for (int w = 1; w < NWARPS; w++) total += red_acc[w];
        g_partial[row] = total;
    }
}

__global__ __launch_bounds__(THREADS)
void perturbed_loss_reduce_kernel(float* __restrict__ out)
{
    __shared__ float red[NWARPS];
    const int tid  = threadIdx.x;
    const int lane = tid & 31;
    const int warp = tid >> 5;

    float acc = 0.0f;
    for (int i = tid; i < NROWS; i += THREADS) acc += g_partial[i];
    #pragma unroll
    for (int o = 16; o; o >>= 1) acc += __shfl_xor_sync(0xffffffffu, acc, o);
    if (lane == 0) red[warp] = acc;
    __syncthreads();
    if (tid == 0) {
        float total = red[0];
        #pragma unroll
        for (int w = 1; w < NWARPS; w++) total += red[w];
        out[0] = total * (1.0f / ((float)NROWS * (float)D_DIM));
    }
}

extern "C" void kernel_launch(void* const* d_in, const int* in_sizes, int n_in,
                              void* d_out, int out_size)
{
    const float* theta = (const float*)d_in[0];  // [B, D]
    const float* y     = (const float*)d_in[1];  // [B, D]
    const float* noise = (const float*)d_in[2];  // [S, B, D]
    float* out = (float*)d_out;

    const size_t smem = D_DIM * sizeof(float);   // 40000 B < 48 KB default limit
    perturbed_loss_row_kernel<<<NROWS, THREADS, smem>>>(theta, y, noise);
    perturbed_loss_reduce_kernel<<<1, THREADS>>>(out);
}

// round 2
// speedup vs baseline: 2.1146x; 2.1146x over previous
#include <cuda_runtime.h>

// S=64, B=128, D=10000 fixed by the reference.
#define D_DIM   10000
#define D4      2500              // float4 per row
#define S_DIM   64
#define B_DIM   128
#define THREADS 512
#define NWARPS  (THREADS / 32)    // 16
#define PER_T   5                 // float4 chunks per thread (512*5=2560 >= 2500)
#define V4LIM   (D4 - 4 * THREADS)   // 452: threads below this have a valid 5th chunk

__device__ float g_partial[B_DIM];

__device__ __forceinline__ void do_sample(
    int s, int b, int tid,
    int lane, int warp,
    const float* __restrict__ noise,
    const float4 (&tv)[PER_T], const float4 (&yv)[PER_T], bool v4,
    float4 (&cur)[PER_T], float4 (&nxt)[PER_T],
    float (*red)[NWARPS], float& acc)
{
    // ---- prefetch noise for sample s+1 into nxt ----
    if (s + 1 < S_DIM) {
        const float4* __restrict__ nz =
            (const float4*)(noise + ((size_t)(s + 1) * B_DIM + b) * D_DIM);
        #pragma unroll
        for (int k = 0; k < PER_T; k++) {
            if (k < PER_T - 1 || v4)
                nxt[k] = __ldcs(&nz[tid + k * THREADS]);
        }
    }

    // ---- pi_unnorm = exp(theta + noise) ; local sum ----
    float4 p[PER_T];
    float lsum = 0.0f;
    #pragma unroll
    for (int k = 0; k < PER_T; k++) {
        if (k == PER_T - 1 && !v4) {
            p[k] = make_float4(0.f, 0.f, 0.f, 0.f);
        } else {
            float4 c = cur[k], t = tv[k];
            float4 q;
            q.x = __expf(t.x + c.x);
            q.y = __expf(t.y + c.y);
            q.z = __expf(t.z + c.z);
            q.w = __expf(t.w + c.w);
            p[k] = q;
            lsum += (q.x + q.y) + (q.z + q.w);
        }
    }

    // ---- block reduction of lsum (single barrier, parity smem buffer) ----
    #pragma unroll
    for (int o = 16; o; o >>= 1)
        lsum += __shfl_xor_sync(0xffffffffu, lsum, o);
    const int par = s & 1;
    if (lane == 0) red[par][warp] = lsum;
    __syncthreads();
    float tot = red[par][0];
    #pragma unroll
    for (int w = 1; w < NWARPS; w++) tot += red[par][w];
    const float inv = __frcp_rn(tot);

    // ---- acc += (pi*inv - y)^2  (no reduction until the very end) ----
    #pragma unroll
    for (int k = 0; k < PER_T; k++) {
        float4 q = p[k], yy = yv[k];
        float dx = fmaf(q.x, inv, -yy.x);
        float dy = fmaf(q.y, inv, -yy.y);
        float dz = fmaf(q.z, inv, -yy.z);
        float dw = fmaf(q.w, inv, -yy.w);
        acc = fmaf(dx, dx, acc);
        acc = fmaf(dy, dy, acc);
        acc = fmaf(dz, dz, acc);
        acc = fmaf(dw, dw, acc);
    }
}

__global__ __launch_bounds__(THREADS, 1)
void pl_main(const float* __restrict__ theta,
             const float* __restrict__ y,
             const float* __restrict__ noise)
{
    __shared__ float red[2][NWARPS];
    __shared__ float fin[NWARPS];

    const int b    = blockIdx.x;
    const int tid  = threadIdx.x;
    const int lane = tid & 31;
    const int warp = tid >> 5;
    const bool v4  = (tid < V4LIM);

    const float4* __restrict__ th4 = (const float4*)(theta + (size_t)b * D_DIM);
    const float4* __restrict__ yy4 = (const float4*)(y     + (size_t)b * D_DIM);

    // theta, y resident in registers for all 64 samples
    float4 tv[PER_T], yv[PER_T];
    #pragma unroll
    for (int k = 0; k < PER_T; k++) {
        if (k < PER_T - 1 || v4) {
            tv[k] = th4[tid + k * THREADS];
            yv[k] = yy4[tid + k * THREADS];
        } else {
            tv[k] = make_float4(0.f, 0.f, 0.f, 0.f);
            yv[k] = make_float4(0.f, 0.f, 0.f, 0.f);
        }
    }

    // prologue: load sample 0 noise
    float4 bufA[PER_T], bufB[PER_T];
    {
        const float4* __restrict__ nz =
            (const float4*)(noise + (size_t)b * D_DIM);
        #pragma unroll
        for (int k = 0; k < PER_T; k++) {
            if (k < PER_T - 1 || v4) bufA[k] = __ldcs(&nz[tid + k * THREADS]);
            else                     bufA[k] = make_float4(0.f, 0.f, 0.f, 0.f);
        }
    }

    float acc = 0.0f;
    #pragma unroll 1
    for (int s = 0; s < S_DIM; s += 2) {
        do_sample(s,     b, tid, lane, warp, noise, tv, yv, v4, bufA, bufB, red, acc);
        do_sample(s + 1, b, tid, lane, warp, noise, tv, yv, v4, bufB, bufA, red, acc);
    }

    // ---- one final block reduction of acc ----
    #pragma unroll
    for (int o = 16; o; o >>= 1)
        acc += __shfl_xor_sync(0xffffffffu, acc, o);
    if (lane == 0) fin[warp] = acc;
    __syncthreads();
    if (tid == 0) {
        float total = fin[0];
        #pragma unroll
        for (int w = 1; w < NWARPS; w++) total += fin[w];
        g_partial[b] = total;
    }
}

__global__ void pl_reduce(float* __restrict__ out)
{
    const int tid = threadIdx.x;          // 128 threads
    __shared__ float red[4];
    float v = g_partial[tid];
    #pragma unroll
    for (int o = 16; o; o >>= 1) v += __shfl_xor_sync(0xffffffffu, v, o);
    if ((tid & 31) == 0) red[tid >> 5] = v;
    __syncthreads();
    if (tid == 0) {
        float t = red[0] + red[1] + red[2] + red[3];
        out[0] = t * (1.0f / ((float)S_DIM * (float)B_DIM * (float)D_DIM));
    }
}

extern "C" void kernel_launch(void* const* d_in, const int* in_sizes, int n_in,
                              void* d_out, int out_size)
{
    const float* theta = (const float*)d_in[0];  // [B, D]
    const float* y     = (const float*)d_in[1];  // [B, D]
    const float* noise = (const float*)d_in[2];  // [S, B, D]
    float* out = (float*)d_out;

    pl_main<<<B_DIM, THREADS>>>(theta, y, noise);
    pl_reduce<<<1, B_DIM>>>(out);
}